// round 11
// baseline (speedup 1.0000x reference)
#include <cuda_runtime.h>

#define T_STEPS 1024
#define BATCH   2048
#define N1      30
#define N2      60

using ull = unsigned long long;

// ---- scratch: pre-reduced y partials (8 lanes per batch-pair-step), 64 MiB ----
__device__ float2 g_ysc[T_STEPS][BATCH / 2][8];

// packed fp32x2 FMA (Blackwell)
__device__ __forceinline__ ull ffma2(ull a, ull b, ull c) {
    ull d;
    asm("fma.rn.f32x2 %0, %1, %2, %3;" : "=l"(d) : "l"(a), "l"(b), "l"(c));
    return d;
}
__device__ __forceinline__ ull pk2(float x, float y) {
    ull r;
    asm("mov.b64 %0, {%1, %2};" : "=l"(r) : "f"(x), "f"(y));
    return r;
}
__device__ __forceinline__ float hadd2(ull v) {
    float a, b;
    asm("mov.b64 {%0, %1}, %2;" : "=f"(a), "=f"(b) : "l"(v));
    return a + b;
}
// fast tanh, ~1e-6 rel err; pre-activations bounded, no clamp needed
__device__ __forceinline__ float ftanh(float x) {
    float e = __expf(-2.f * x);
    return __fdividef(1.f - e, 1.f + e);
}

#define W11S 34   // smem row stride for W11

// Block = 32 threads = ONE warp owning batch pair (b0, b0+1).  (R10 logic, balanced grid)
__global__ void __launch_bounds__(32) hier_rnn_kernel(
    const float* __restrict__ inp,    // (T, B, 1)
    const float* __restrict__ noise1, // (T, B, N1)
    const float* __restrict__ noise2, // (T, B, N2)
    const float* __restrict__ W11,    // (N1, N1)
    const float* __restrict__ W22,    // (N2, N2)
    const float* __restrict__ W21,    // (N2, N1)
    const float* __restrict__ M21,    // (N2, N1)
    const float* __restrict__ Win,    // (N1,)
    const float* __restrict__ Wout)   // (N2,)
{
    __shared__ __align__(16) float s1_0[32], s1_1[32];   // r1 per elem (pads 30,31 = 0)
    __shared__ __align__(16) float s2_0[64], s2_1[64];   // r2 per elem (pads 60..63 = 0)
    __shared__ __align__(8)  float sW11[N1][W11S];       // cols 30..33 zero

    const int l  = threadIdx.x;
    const int gw = blockIdx.x;        // batch-pair index
    const int b0 = gw * 2;

    const bool act = (l < N1);
    const int  ls  = act ? l : 0;
    const int  ra  = 2 * ls;
    const int  rb  = 2 * ls + 1;

    // ---- W21m + W22 in registers (180 regs); W11 in smem ----
    ull w21ap[15], w21bp[15], w22ap[30], w22bp[30];
    #pragma unroll
    for (int k = 0; k < 15; k++) {
        float2 w = act ? *(const float2*)(W21 + ra * N1 + 2 * k) : make_float2(0.f, 0.f);
        float2 m = act ? *(const float2*)(M21 + ra * N1 + 2 * k) : make_float2(0.f, 0.f);
        w21ap[k] = pk2(w.x * m.x, w.y * m.y);
        w = act ? *(const float2*)(W21 + rb * N1 + 2 * k) : make_float2(0.f, 0.f);
        m = act ? *(const float2*)(M21 + rb * N1 + 2 * k) : make_float2(0.f, 0.f);
        w21bp[k] = pk2(w.x * m.x, w.y * m.y);
    }
    #pragma unroll
    for (int k = 0; k < 30; k++) {
        float2 w = act ? *(const float2*)(W22 + ra * N2 + 2 * k) : make_float2(0.f, 0.f);
        w22ap[k] = pk2(w.x, w.y);
        w = act ? *(const float2*)(W22 + rb * N2 + 2 * k) : make_float2(0.f, 0.f);
        w22bp[k] = pk2(w.x, w.y);
    }
    const float winl  = act ? Win[l]   : 0.f;
    const float wouta = act ? Wout[ra] : 0.f;
    const float woutb = act ? Wout[rb] : 0.f;

    // ---- W11 smem table ----
    for (int idx = l; idx < N1 * W11S; idx += 32) {
        int r = idx / W11S, c = idx - r * W11S;
        sW11[r][c] = (c < N1) ? W11[r * N1 + c] : 0.f;
    }

    // ---- zero state ----
    s1_0[l] = 0.f; s1_1[l] = 0.f;
    s2_0[l] = 0.f; s2_0[l + 32] = 0.f;
    s2_1[l] = 0.f; s2_1[l + 32] = 0.f;
    __syncwarp();

    const float* rw = &sW11[ls][0];

    // ---- streaming pointers ----
    const float* pn1 = noise1 + (long long)b0 * N1 + ls;
    const float* pn2 = noise2 + (long long)b0 * N2 + ra;
    const float* px  = inp + b0;

    float2 xv   = *(const float2*)px;
    float  n1v0 = __ldg(pn1);
    float  n1v1 = __ldg(pn1 + N1);
    float2 n2v0 = *(const float2*)pn2;
    float2 n2v1 = *(const float2*)(pn2 + N2);

    const ulonglong2* v1_0 = (const ulonglong2*)s1_0;
    const ulonglong2* v1_1 = (const ulonglong2*)s1_1;
    const ulonglong2* v2_0 = (const ulonglong2*)s2_0;
    const ulonglong2* v2_1 = (const ulonglong2*)s2_1;
    const ull* s1w_0 = (const ull*)s1_0;
    const ull* s1w_1 = (const ull*)s1_1;

    for (int t = 0; t < T_STEPS; t++) {
        // one-step-ahead prefetch (covers DRAM latency)
        float2 xn  = make_float2(0.f, 0.f);
        float  n1n0 = 0.f, n1n1 = 0.f;
        float2 n2n0 = make_float2(0.f, 0.f), n2n1 = make_float2(0.f, 0.f);
        if (t + 1 < T_STEPS) {
            px  += BATCH;
            pn1 += BATCH * N1;
            pn2 += BATCH * N2;
            xn   = *(const float2*)px;
            n1n0 = __ldg(pn1);
            n1n1 = __ldg(pn1 + N1);
            n2n0 = *(const float2*)pn2;
            n2n1 = *(const float2*)(pn2 + N2);
        }

        // ---- phase A: W22 . r2_old, 4 independent chains ----
        ull a2a0 = 0, a2b0 = 0, a2a1 = 0, a2b1 = 0;
        #pragma unroll
        for (int k = 0; k < 15; k++) {
            ulonglong2 u0 = v2_0[k];
            ulonglong2 u1 = v2_1[k];
            a2a0 = ffma2(w22ap[2 * k],     u0.x, a2a0);
            a2a0 = ffma2(w22ap[2 * k + 1], u0.y, a2a0);
            a2b0 = ffma2(w22bp[2 * k],     u0.x, a2b0);
            a2b0 = ffma2(w22bp[2 * k + 1], u0.y, a2b0);
            a2a1 = ffma2(w22ap[2 * k],     u1.x, a2a1);
            a2a1 = ffma2(w22ap[2 * k + 1], u1.y, a2a1);
            a2b1 = ffma2(w22bp[2 * k],     u1.x, a2b1);
            a2b1 = ffma2(w22bp[2 * k + 1], u1.y, a2b1);
        }

        // ---- phase B: r1 update, W11 from smem ----
        ull a1_0 = 0, a1_1 = 0;
        #pragma unroll
        for (int k = 0; k < 7; k++) {
            float2 wx = *(const float2*)(rw + 4 * k);
            float2 wy = *(const float2*)(rw + 4 * k + 2);
            ull wX = pk2(wx.x, wx.y), wY = pk2(wy.x, wy.y);
            ulonglong2 u0 = v1_0[k];
            ulonglong2 u1 = v1_1[k];
            a1_0 = ffma2(wX, u0.x, a1_0);
            a1_0 = ffma2(wY, u0.y, a1_0);
            a1_1 = ffma2(wX, u1.x, a1_1);
            a1_1 = ffma2(wY, u1.y, a1_1);
        }
        {
            float2 wt = *(const float2*)(rw + 28);
            ull wT = pk2(wt.x, wt.y);
            a1_0 = ffma2(wT, s1w_0[14], a1_0);
            a1_1 = ffma2(wT, s1w_1[14], a1_1);
        }

        float r1n0 = ftanh(fmaf(winl, xv.x, n1v0) + hadd2(a1_0));
        float r1n1 = ftanh(fmaf(winl, xv.y, n1v1) + hadd2(a1_1));

        __syncwarp();                    // sync1: all old-state reads (A and B) done
        if (act) { s1_0[l] = r1n0; s1_1[l] = r1n1; }
        __syncwarp();                    // sync2: r1_new visible

        // ---- phase C: += W21m . r1_new ----
        #pragma unroll
        for (int k = 0; k < 7; k++) {
            ulonglong2 u0 = v1_0[k];
            ulonglong2 u1 = v1_1[k];
            a2a0 = ffma2(w21ap[2 * k],     u0.x, a2a0);
            a2b0 = ffma2(w21bp[2 * k],     u0.x, a2b0);
            a2a1 = ffma2(w21ap[2 * k],     u1.x, a2a1);
            a2b1 = ffma2(w21bp[2 * k],     u1.x, a2b1);
            a2a0 = ffma2(w21ap[2 * k + 1], u0.y, a2a0);
            a2b0 = ffma2(w21bp[2 * k + 1], u0.y, a2b0);
            a2a1 = ffma2(w21ap[2 * k + 1], u1.y, a2a1);
            a2b1 = ffma2(w21bp[2 * k + 1], u1.y, a2b1);
        }
        {
            ull u0 = s1w_0[14];
            ull u1 = s1w_1[14];
            a2a0 = ffma2(w21ap[14], u0, a2a0);
            a2b0 = ffma2(w21bp[14], u0, a2b0);
            a2a1 = ffma2(w21ap[14], u1, a2a1);
            a2b1 = ffma2(w21bp[14], u1, a2b1);
        }

        float r2a0 = ftanh(n2v0.x + hadd2(a2a0));
        float r2b0 = ftanh(n2v0.y + hadd2(a2b0));
        float r2a1 = ftanh(n2v1.x + hadd2(a2a1));
        float r2b1 = ftanh(n2v1.y + hadd2(a2b1));

        // publish r2 (old-r2 reads were all before sync1)
        if (act) {
            *(float2*)(s2_0 + ra) = make_float2(r2a0, r2b0);
            *(float2*)(s2_1 + ra) = make_float2(r2a1, r2b1);
        }

        // ---- y partials: 2-level pre-reduction, then streaming store of 8 lanes ----
        float yp0 = wouta * r2a0 + woutb * r2b0;   // 0 on inactive lanes
        float yp1 = wouta * r2a1 + woutb * r2b1;
        yp0 += __shfl_xor_sync(0xffffffffu, yp0, 16);
        yp1 += __shfl_xor_sync(0xffffffffu, yp1, 16);
        yp0 += __shfl_xor_sync(0xffffffffu, yp0, 8);
        yp1 += __shfl_xor_sync(0xffffffffu, yp1, 8);
        if (l < 8) __stcs(&g_ysc[t][gw][l], make_float2(yp0, yp1));

        __syncwarp();                    // sync3: r2_new visible before next step's reads

        xv = xn; n1v0 = n1n0; n1v1 = n1n1; n2v0 = n2n0; n2v1 = n2n1;
    }
}

// grid-stride reducer: sum 8 partials -> y[t][b] for all (t, batch-pair)
__global__ void __launch_bounds__(256) reduce_y(float* __restrict__ out)
{
    const int l      = threadIdx.x & 31;
    const int wid    = (blockIdx.x * blockDim.x + threadIdx.x) >> 5;
    const int nwarps = (gridDim.x * blockDim.x) >> 5;
    const int ntasks = T_STEPS * (BATCH / 2) / 4;   // 4 groups per warp

    for (int task = wid; task < ntasks; task += nwarps) {
        int g  = task * 4 + (l >> 3);
        int j  = l & 7;
        int t  = g >> 10;
        int wp = g & 1023;
        float2 v = __ldcs(&g_ysc[t][wp][j]);
        v.x += __shfl_xor_sync(0xffffffffu, v.x, 4);
        v.y += __shfl_xor_sync(0xffffffffu, v.y, 4);
        v.x += __shfl_xor_sync(0xffffffffu, v.x, 2);
        v.y += __shfl_xor_sync(0xffffffffu, v.y, 2);
        v.x += __shfl_xor_sync(0xffffffffu, v.x, 1);
        v.y += __shfl_xor_sync(0xffffffffu, v.y, 1);
        if (j == 0) *(float2*)(out + t * BATCH + 2 * wp) = v;
    }
}

extern "C" void kernel_launch(void* const* d_in, const int* in_sizes, int n_in,
                              void* d_out, int out_size)
{
    const float *inp = nullptr, *n1 = nullptr, *n2 = nullptr;
    const float *W11 = nullptr, *W22 = nullptr, *W21 = nullptr, *M21 = nullptr;
    const float *Win = nullptr, *Wout = nullptr;

    for (int i = 0; i < n_in; i++) {
        const float* p = (const float*)d_in[i];
        switch (in_sizes[i]) {
            case T_STEPS * BATCH:          inp = p; break;
            case T_STEPS * BATCH * N1:     n1  = p; break;
            case T_STEPS * BATCH * N2:     n2  = p; break;
            case N1 * N1:                  W11 = p; break;
            case N2 * N2:                  W22 = p; break;
            case N2 * N1:                                   // appears twice (W21, mask)
                if (!W21) W21 = p; else M21 = p;            // product commutes
                break;
            case N1:                       Win = p; break;
            case N2:                       Wout = p; break;
        }
    }

    // 1024 single-warp blocks, 2 batch elems each -> balanced 6-7 warps/SM
    hier_rnn_kernel<<<BATCH / 2, 32>>>(inp, n1, n2, W11, W22, W21, M21, Win, Wout);
    // persistent grid-stride reduction of the pre-reduced partials
    reduce_y<<<1184, 256>>>((float*)d_out);
}